// round 15
// baseline (speedup 1.0000x reference)
#include <cuda_runtime.h>
#include <cuda_fp16.h>

#define NN 100000
#define EE 800000
#define NB 98            // scan blocks: ceil(100000/1024)

// ---------------- scratch (device globals; BSS = zero-initialized) ----------
__device__ unsigned g_hh[NN * 64];      // projected features, packed half2 (fp16)
__device__ float    g_feat2[NN * 128];  // relu(out1 + b1) -> layer-2 input (fp32)
__device__ float    g_el[NN * 4];
__device__ float    g_er[NN * 4];
__device__ int      g_cnt[NN];          // INVARIANT: zero at entry of each call
__device__ int      g_off[NN + 1];      // CSR row offsets (by dst)
__device__ int      g_rank[EE];         // intra-node rank of each edge
__device__ int      g_esrc[EE];         // src node per CSR slot
__device__ int      g_bsum[NB];
__device__ int      g_ctr;              // grid-barrier counter; self-resets to 0
// W as packed fp16 pairs (k, k+1) along K: [layer][ (k/2)*128 + n ]
__device__ unsigned g_Wh[2][64 * 128];

__device__ __forceinline__ float lrelu(float v) { return v > 0.f ? v : 0.2f * v; }

// pack two fp32 into one f16x2 (low half = x0, high half = x1)
__device__ __forceinline__ unsigned pack_f16(float x0, float x1) {
    unsigned p;
    asm("cvt.rn.f16x2.f32 %0, %1, %2;" : "=r"(p) : "f"(x1), "f"(x0));
    return p;
}

#define MMA_F16(c, a0, a1, a2, a3, b0, b1)                                     \
    asm volatile(                                                              \
        "mma.sync.aligned.m16n8k16.row.col.f32.f16.f16.f32 "                   \
        "{%0,%1,%2,%3}, {%4,%5,%6,%7}, {%8,%9}, {%0,%1,%2,%3};"                \
        : "+f"(c[0]), "+f"(c[1]), "+f"(c[2]), "+f"(c[3])                       \
        : "r"(a0), "r"(a1), "r"(a2), "r"(a3), "r"(b0), "r"(b1))

// ---------------- fused: W pack (fp16) + edge count/rank --------------------
__global__ void k_pc(const float* __restrict__ W1, const float* __restrict__ W2,
                     const int* __restrict__ dst) {
    int i = blockIdx.x * 256 + threadIdx.x;
    if (i < 2 * 64 * 128) {
        int which = i >> 13, j = i & 8191;
        int kp = j >> 7, n = j & 127;
        const float* W = which == 0 ? W1 : W2;
        g_Wh[which][kp * 128 + n] =
            pack_f16(W[(2 * kp) * 128 + n], W[(2 * kp + 1) * 128 + n]);
    }
    if (i < EE) g_rank[i] = atomicAdd(&g_cnt[dst[i]], 1);
}

// ---------------- single-kernel CSR offset scan (grid barrier) --------------
__global__ void __launch_bounds__(1024) k_scan() {
    __shared__ int sh[1024];
    __shared__ int bs[128];
    int t = threadIdx.x, i = blockIdx.x * 1024 + t;
    int v = (i < NN) ? g_cnt[i] : 0;
    if (i < NN) g_cnt[i] = 0;               // restore invariant for next call
    sh[t] = v; __syncthreads();
#pragma unroll
    for (int d = 1; d < 1024; d <<= 1) {
        int add = (t >= d) ? sh[t - d] : 0;
        __syncthreads();
        sh[t] += add;
        __syncthreads();
    }
    if (t == 1023) {
        g_bsum[blockIdx.x] = sh[1023];
        __threadfence();
        atomicAdd(&g_ctr, 1);
    }
    if (t == 0) {
        while (*(volatile int*)&g_ctr < NB) { }
        __threadfence();
    }
    __syncthreads();
    if (t < 128) bs[t] = (t < NB) ? g_bsum[t] : 0;
    __syncthreads();
#pragma unroll
    for (int d = 1; d < 128; d <<= 1) {
        int add = 0;
        if (t < 128 && t >= d) add = bs[t - d];
        __syncthreads();
        if (t < 128) bs[t] += add;
        __syncthreads();
    }
    int add = blockIdx.x > 0 ? bs[blockIdx.x - 1] : 0;
    if (i < NN) g_off[i] = sh[t] - v + add;   // exclusive prefix
    if (i == 0) g_off[NN] = EE;
    __syncthreads();
    if (t == 0) {
        int old = atomicAdd(&g_ctr, 1);       // phase-2 count: NB..2*NB
        if (old == 2 * NB - 1) atomicExch(&g_ctr, 0);   // last block resets
    }
}

// fill without atomics: position = off[dst] + rank
__global__ void k_fill(const int* __restrict__ src, const int* __restrict__ dst) {
    int e = blockIdx.x * 256 + threadIdx.x;
    if (e >= EE) return;
    int p = g_off[dst[e]] + g_rank[e];
    g_esrc[p] = src[e];
}

// ---------------- tensor-core projection GEMM (fp16, pipelined) -------------
// 64 rows x 128 cols per block; 8 warps 4(row)x2(col). Full W resident in
// smem (loaded once); X double-buffered with 1 sync/chunk; gmem fetch of
// chunk c+1 overlaps MMA of chunk c. Fused el/er epilogue; h stored fp16.
__global__ void __launch_bounds__(256) k_gemm_tc(
    const float* __restrict__ xext, int use_internal, int widx,
    const float* __restrict__ al, const float* __restrict__ ar)
{
    const float* x = use_internal ? g_feat2 : xext;
    const unsigned* Wg = g_Wh[widx];

    __shared__ unsigned Whs[64][136];     // full W: 64 kpairs x 128 n (+8 pad)
    __shared__ unsigned Xh[2][64][20];    // double-buffered X chunk

    int t = threadIdx.x;
    int lane = t & 31, w = t >> 5;
    int row0 = blockIdx.x * 64;
    int wr = (w >> 1) * 16;            // warp row base (4 row groups)
    int wc = (w & 1) * 64;             // warp col base (2 col halves)
    int gq = lane >> 2, qc = lane & 3;

    // full W load: 2048 uint4 over 256 threads = 8 each
#pragma unroll
    for (int l = 0; l < 8; l++) {
        int idx = t + l * 256;
        int kk = idx >> 5, c4 = idx & 31;
        *(uint4*)&Whs[kk][c4 * 4] = ((const uint4*)(Wg + kk * 128))[c4];
    }

    // per-thread fixed X slots: rows xr, xr+32, float4 column xc
    int xr = t >> 3, xc = t & 7;
    bool ok0 = (row0 + xr) < NN, ok1 = (row0 + xr + 32) < NN;
    const float4* xp0 = (const float4*)(x + (row0 + xr) * 128);
    const float4* xp1 = (const float4*)(x + (row0 + xr + 32) * 128);
    float4 v0, v1;
    const float4 z4 = make_float4(0.f, 0.f, 0.f, 0.f);

    // fetch + store chunk 0
    v0 = ok0 ? xp0[xc] : z4;
    v1 = ok1 ? xp1[xc] : z4;
    Xh[0][xr][xc * 2]          = pack_f16(v0.x, v0.y);
    Xh[0][xr][xc * 2 + 1]      = pack_f16(v0.z, v0.w);
    Xh[0][xr + 32][xc * 2]     = pack_f16(v1.x, v1.y);
    Xh[0][xr + 32][xc * 2 + 1] = pack_f16(v1.z, v1.w);

    float acc[8][4];
#pragma unroll
    for (int nt = 0; nt < 8; nt++)
#pragma unroll
        for (int j = 0; j < 4; j++) acc[nt][j] = 0.f;

#pragma unroll
    for (int c = 0; c < 4; c++) {
        __syncthreads();   // chunk-c stores visible; prior reads of next buf done
        if (c < 3) {       // prefetch chunk c+1 (latency hidden by MMA below)
            int cc4 = (c + 1) * 8 + xc;
            v0 = ok0 ? xp0[cc4] : z4;
            v1 = ok1 ? xp1[cc4] : z4;
        }
        int kp0 = c * 16;
        int buf = c & 1;
#pragma unroll
        for (int ks = 0; ks < 2; ks++) {
            int kb = ks * 8;
            unsigned a0 = Xh[buf][wr + gq][kb + qc];
            unsigned a1 = Xh[buf][wr + gq + 8][kb + qc];
            unsigned a2 = Xh[buf][wr + gq][kb + qc + 4];
            unsigned a3 = Xh[buf][wr + gq + 8][kb + qc + 4];
#pragma unroll
            for (int nt = 0; nt < 8; nt++) {
                int nb = wc + nt * 8 + gq;
                unsigned b0 = Whs[kp0 + kb + qc][nb];
                unsigned b1 = Whs[kp0 + kb + qc + 4][nb];
                MMA_F16(acc[nt], a0, a1, a2, a3, b0, b1);
            }
        }
        if (c < 3) {
            int nbuf = (c + 1) & 1;
            Xh[nbuf][xr][xc * 2]          = pack_f16(v0.x, v0.y);
            Xh[nbuf][xr][xc * 2 + 1]      = pack_f16(v0.z, v0.w);
            Xh[nbuf][xr + 32][xc * 2]     = pack_f16(v1.x, v1.y);
            Xh[nbuf][xr + 32][xc * 2 + 1] = pack_f16(v1.z, v1.w);
        }
    }

    // ---- epilogue: store h (fp16 half2), compute el/er for 2 heads ----
    int n0 = row0 + wr + gq;
    int n1 = n0 + 8;
    int hdb = wc >> 5;                    // head base: 0 (cols 0-63) or 2
    float pel0[2], per0[2], pel1[2], per1[2];
#pragma unroll
    for (int lh = 0; lh < 2; lh++) { pel0[lh] = per0[lh] = pel1[lh] = per1[lh] = 0.f; }

#pragma unroll
    for (int nt = 0; nt < 8; nt++) {
        int col = wc + nt * 8 + 2 * qc;
        float a0 = al[col], a1 = al[col + 1];
        float r0 = ar[col], r1 = ar[col + 1];
        int lh = nt >> 2;
        pel0[lh] += acc[nt][0] * a0 + acc[nt][1] * a1;
        per0[lh] += acc[nt][0] * r0 + acc[nt][1] * r1;
        pel1[lh] += acc[nt][2] * a0 + acc[nt][3] * a1;
        per1[lh] += acc[nt][2] * r0 + acc[nt][3] * r1;
        if (n0 < NN) {
            __half2 hp = __float22half2_rn(make_float2(acc[nt][0], acc[nt][1]));
            g_hh[n0 * 64 + (col >> 1)] = *reinterpret_cast<unsigned*>(&hp);
        }
        if (n1 < NN) {
            __half2 hp = __float22half2_rn(make_float2(acc[nt][2], acc[nt][3]));
            g_hh[n1 * 64 + (col >> 1)] = *reinterpret_cast<unsigned*>(&hp);
        }
    }
#pragma unroll
    for (int lh = 0; lh < 2; lh++) {
#pragma unroll
        for (int o = 1; o <= 2; o <<= 1) {
            pel0[lh] += __shfl_xor_sync(0xffffffffu, pel0[lh], o);
            per0[lh] += __shfl_xor_sync(0xffffffffu, per0[lh], o);
            pel1[lh] += __shfl_xor_sync(0xffffffffu, pel1[lh], o);
            per1[lh] += __shfl_xor_sync(0xffffffffu, per1[lh], o);
        }
    }
    if (qc == 0) {
#pragma unroll
        for (int lh = 0; lh < 2; lh++) {
            int hd = hdb + lh;
            if (n0 < NN) { g_el[n0 * 4 + hd] = pel0[lh]; g_er[n0 * 4 + hd] = per0[lh]; }
            if (n1 < NN) { g_el[n1 * 4 + hd] = pel1[lh]; g_er[n1 * 4 + hd] = per1[lh]; }
        }
    }
}

// ---------------- fused softmax + aggregation: 2 nodes per warp -------------
// 16 lanes per node; lane covers 8 feats via one uint4 (fp16x8) per edge.
// No softmax shift needed: logits are O(5) (el,er each sigma~0.5), exp safe.
__global__ void __launch_bounds__(256) k_node(
    const float* __restrict__ b, float* __restrict__ out, int layer)
{
    int gwarp = (blockIdx.x * 256 + threadIdx.x) >> 5;
    int lane = threadIdx.x & 31;
    int half = lane >> 4, sl = lane & 15;
    int n = gwarp * 2 + half;
    bool act = n < NN;
    int hd = sl >> 2;

    int off = 0, deg = 0;
    if (act) {
        off = g_off[n];
        deg = g_off[n + 1] - off;
    }
    float erh = act ? g_er[n * 4 + hd] : 0.f;

    const int*   es = g_esrc + off;
    const uint4* hb = (const uint4*)g_hh;   // 16 uint4 per node
    const float* el = g_el;

    int dmax = max(deg, __shfl_xor_sync(0xffffffffu, deg, 16));

    float s = 0.f;
    float acc[8];
#pragma unroll
    for (int k = 0; k < 8; k++) acc[k] = 0.f;

    for (int j = 0; j < dmax; j += 4) {
        int s0 = (j + 0 < deg) ? es[j + 0] : -1;
        int s1 = (j + 1 < deg) ? es[j + 1] : -1;
        int s2 = (j + 2 < deg) ? es[j + 2] : -1;
        int s3 = (j + 3 < deg) ? es[j + 3] : -1;
        float e0 = (s0 >= 0) ? el[s0 * 4 + hd] : 0.f;
        float e1 = (s1 >= 0) ? el[s1 * 4 + hd] : 0.f;
        float e2 = (s2 >= 0) ? el[s2 * 4 + hd] : 0.f;
        float e3 = (s3 >= 0) ? el[s3 * 4 + hd] : 0.f;
        uint4 z = make_uint4(0u, 0u, 0u, 0u);
        uint4 p0 = (s0 >= 0) ? hb[s0 * 16 + sl] : z;
        uint4 p1 = (s1 >= 0) ? hb[s1 * 16 + sl] : z;
        uint4 p2 = (s2 >= 0) ? hb[s2 * 16 + sl] : z;
        uint4 p3 = (s3 >= 0) ? hb[s3 * 16 + sl] : z;
        float a0 = (s0 >= 0) ? __expf(lrelu(e0 + erh)) : 0.f;
        float a1 = (s1 >= 0) ? __expf(lrelu(e1 + erh)) : 0.f;
        float a2 = (s2 >= 0) ? __expf(lrelu(e2 + erh)) : 0.f;
        float a3 = (s3 >= 0) ? __expf(lrelu(e3 + erh)) : 0.f;
        s += (a0 + a1) + (a2 + a3);
        const unsigned* q0 = &p0.x;
        const unsigned* q1 = &p1.x;
        const unsigned* q2 = &p2.x;
        const unsigned* q3 = &p3.x;
#pragma unroll
        for (int k = 0; k < 4; k++) {
            float2 f0 = __half22float2(*reinterpret_cast<const __half2*>(&q0[k]));
            float2 f1 = __half22float2(*reinterpret_cast<const __half2*>(&q1[k]));
            float2 f2 = __half22float2(*reinterpret_cast<const __half2*>(&q2[k]));
            float2 f3 = __half22float2(*reinterpret_cast<const __half2*>(&q3[k]));
            acc[2 * k]     += (f0.x * a0 + f1.x * a1) + (f2.x * a2 + f3.x * a3);
            acc[2 * k + 1] += (f0.y * a0 + f1.y * a1) + (f2.y * a2 + f3.y * a3);
        }
    }

    float rinv = (act && deg > 0) ? 1.f / s : 0.f;
#pragma unroll
    for (int k = 0; k < 8; k++) acc[k] *= rinv;

    // bias: feats sl*8 .. sl*8+7
    float4 b0 = ((const float4*)b)[sl * 2];
    float4 b1 = ((const float4*)b)[sl * 2 + 1];
    acc[0] += b0.x; acc[1] += b0.y; acc[2] += b0.z; acc[3] += b0.w;
    acc[4] += b1.x; acc[5] += b1.y; acc[6] += b1.z; acc[7] += b1.w;

    if (layer == 1) {
        if (act) {
            float4 o0 = make_float4(fmaxf(acc[0], 0.f), fmaxf(acc[1], 0.f),
                                    fmaxf(acc[2], 0.f), fmaxf(acc[3], 0.f));
            float4 o1 = make_float4(fmaxf(acc[4], 0.f), fmaxf(acc[5], 0.f),
                                    fmaxf(acc[6], 0.f), fmaxf(acc[7], 0.f));
            float4* dst = (float4*)(g_feat2 + n * 128 + sl * 8);
            dst[0] = o0; dst[1] = o1;
        }
    } else {
        // head mean: lanes {sl, sl^4, sl^8, sl^12} hold the 4 heads of the
        // same within-head offsets (sl&3)*8..+7
#pragma unroll
        for (int o = 4; o <= 8; o <<= 1) {
#pragma unroll
            for (int k = 0; k < 8; k++)
                acc[k] += __shfl_xor_sync(0xffffffffu, acc[k], o);
        }
        if (act && sl < 4) {
            float4 o0 = make_float4(acc[0] * 0.25f, acc[1] * 0.25f,
                                    acc[2] * 0.25f, acc[3] * 0.25f);
            float4 o1 = make_float4(acc[4] * 0.25f, acc[5] * 0.25f,
                                    acc[6] * 0.25f, acc[7] * 0.25f);
            float4* dst = (float4*)(out + n * 32 + sl * 8);
            dst[0] = o0; dst[1] = o1;
        }
    }
}

// ---------------- launch ---------------------------------------------------
extern "C" void kernel_launch(void* const* d_in, const int* in_sizes, int n_in,
                              void* d_out, int out_size)
{
    const float* feat = (const float*)d_in[0];
    const int*   src  = (const int*)d_in[1];
    const int*   dst  = (const int*)d_in[2];
    const float* W1   = (const float*)d_in[3];
    const float* al1  = (const float*)d_in[4];
    const float* ar1  = (const float*)d_in[5];
    const float* b1   = (const float*)d_in[6];
    const float* W2   = (const float*)d_in[7];
    const float* al2  = (const float*)d_in[8];
    const float* ar2  = (const float*)d_in[9];
    const float* b2   = (const float*)d_in[10];
    float* out = (float*)d_out;

    const int G_E    = (EE + 255) / 256;
    const int G_GEMM = (NN + 63) / 64;
    const int G_NODE = ((NN + 1) / 2 * 32 + 255) / 256;   // 2 nodes per warp

    k_pc<<<G_E, 256>>>(W1, W2, dst);                     // 0
    k_scan<<<NB, 1024>>>();                              // 1
    k_fill<<<G_E, 256>>>(src, dst);                      // 2
    k_gemm_tc<<<G_GEMM, 256>>>(feat, 0, 0, al1, ar1);    // 3
    k_node<<<G_NODE, 256>>>(b1, nullptr, 1);             // 4
    k_gemm_tc<<<G_GEMM, 256>>>(nullptr, 1, 1, al2, ar2); // 5
    k_node<<<G_NODE, 256>>>(b2, out, 2);                 // 6
}

// round 16
// speedup vs baseline: 1.0260x; 1.0260x over previous
#include <cuda_runtime.h>
#include <cuda_fp16.h>

#define NN 100000
#define EE 800000
#define NB 98            // scan blocks: ceil(100000/1024)

// ---------------- scratch (device globals; BSS = zero-initialized) ----------
__device__ unsigned g_hh[NN * 64];      // projected features, packed half2 (fp16)
__device__ unsigned g_f2h[NN * 64];     // layer-2 input, packed half2 (fp16, kpairs)
__device__ float    g_el[NN * 4];
__device__ float    g_er[NN * 4];
__device__ int      g_cnt[NN];          // INVARIANT: zero at entry of each call
__device__ int      g_off[NN + 1];      // CSR row offsets (by dst)
__device__ int      g_rank[EE];         // intra-node rank of each edge
__device__ int      g_esrc[EE];         // src node per CSR slot
__device__ int      g_bsum[NB];
__device__ int      g_ctr;              // grid-barrier counter; self-resets to 0
// W as packed fp16 pairs (k, k+1) along K: [layer][ (k/2)*128 + n ]
__device__ unsigned g_Wh[2][64 * 128];

__device__ __forceinline__ float lrelu(float v) { return v > 0.f ? v : 0.2f * v; }

// pack two fp32 into one f16x2 (low half = x0, high half = x1)
__device__ __forceinline__ unsigned pack_f16(float x0, float x1) {
    unsigned p;
    asm("cvt.rn.f16x2.f32 %0, %1, %2;" : "=r"(p) : "f"(x1), "f"(x0));
    return p;
}

#define MMA_F16(c, a0, a1, a2, a3, b0, b1)                                     \
    asm volatile(                                                              \
        "mma.sync.aligned.m16n8k16.row.col.f32.f16.f16.f32 "                   \
        "{%0,%1,%2,%3}, {%4,%5,%6,%7}, {%8,%9}, {%0,%1,%2,%3};"                \
        : "+f"(c[0]), "+f"(c[1]), "+f"(c[2]), "+f"(c[3])                       \
        : "r"(a0), "r"(a1), "r"(a2), "r"(a3), "r"(b0), "r"(b1))

// ---------------- fused: W pack (fp16) + edge count/rank --------------------
__global__ void k_pc(const float* __restrict__ W1, const float* __restrict__ W2,
                     const int* __restrict__ dst) {
    int i = blockIdx.x * 256 + threadIdx.x;
    if (i < 2 * 64 * 128) {
        int which = i >> 13, j = i & 8191;
        int kp = j >> 7, n = j & 127;
        const float* W = which == 0 ? W1 : W2;
        g_Wh[which][kp * 128 + n] =
            pack_f16(W[(2 * kp) * 128 + n], W[(2 * kp + 1) * 128 + n]);
    }
    if (i < EE) g_rank[i] = atomicAdd(&g_cnt[dst[i]], 1);
}

// ---------------- single-kernel CSR offset scan (grid barrier) --------------
__global__ void __launch_bounds__(1024) k_scan() {
    __shared__ int sh[1024];
    __shared__ int bs[128];
    int t = threadIdx.x, i = blockIdx.x * 1024 + t;
    int v = (i < NN) ? g_cnt[i] : 0;
    if (i < NN) g_cnt[i] = 0;               // restore invariant for next call
    sh[t] = v; __syncthreads();
#pragma unroll
    for (int d = 1; d < 1024; d <<= 1) {
        int add = (t >= d) ? sh[t - d] : 0;
        __syncthreads();
        sh[t] += add;
        __syncthreads();
    }
    if (t == 1023) {
        g_bsum[blockIdx.x] = sh[1023];
        __threadfence();
        atomicAdd(&g_ctr, 1);
    }
    if (t == 0) {
        while (*(volatile int*)&g_ctr < NB) { }
        __threadfence();
    }
    __syncthreads();
    if (t < 128) bs[t] = (t < NB) ? g_bsum[t] : 0;
    __syncthreads();
#pragma unroll
    for (int d = 1; d < 128; d <<= 1) {
        int add = 0;
        if (t < 128 && t >= d) add = bs[t - d];
        __syncthreads();
        if (t < 128) bs[t] += add;
        __syncthreads();
    }
    int add = blockIdx.x > 0 ? bs[blockIdx.x - 1] : 0;
    if (i < NN) g_off[i] = sh[t] - v + add;   // exclusive prefix
    if (i == 0) g_off[NN] = EE;
    __syncthreads();
    if (t == 0) {
        int old = atomicAdd(&g_ctr, 1);       // phase-2 count: NB..2*NB
        if (old == 2 * NB - 1) atomicExch(&g_ctr, 0);   // last block resets
    }
}

// fill without atomics: position = off[dst] + rank
__global__ void k_fill(const int* __restrict__ src, const int* __restrict__ dst) {
    int e = blockIdx.x * 256 + threadIdx.x;
    if (e >= EE) return;
    int p = g_off[dst[e]] + g_rank[e];
    g_esrc[p] = src[e];
}

// ---------------- tensor-core projection GEMM (fp16) ------------------------
// 128 rows x 128 cols per block; 8 warps 4(row)x2(col); warp = 32 rows x 64
// cols (2 m16 row-tiles sharing each B fragment -> B-LDS per row halved).
// Layer 1 reads fp32 x; layer 2 reads fp16-packed g_f2h. Fused el/er.
__global__ void __launch_bounds__(256, 2) k_gemm_tc(
    const float* __restrict__ xext, int use_internal, int widx,
    const float* __restrict__ al, const float* __restrict__ ar)
{
    const unsigned* Wg = g_Wh[widx];

    __shared__ unsigned Whs[64][136];     // full W: 64 kpairs x 128 n (+8 pad)
    __shared__ unsigned Xh[128][20];      // X chunk: 128 rows x 16 kpairs (+4)

    int t = threadIdx.x;
    int lane = t & 31, w = t >> 5;
    int row0 = blockIdx.x * 128;
    int wr = (w >> 1) * 32;            // warp row base (4 row groups of 32)
    int wc = (w & 1) * 64;             // warp col base (2 col halves)
    int gq = lane >> 2, qc = lane & 3;

    // full W load: 2048 uint4 over 256 threads = 8 each
#pragma unroll
    for (int l = 0; l < 8; l++) {
        int idx = t + l * 256;
        int kk = idx >> 5, c4 = idx & 31;
        *(uint4*)&Whs[kk][c4 * 4] = ((const uint4*)(Wg + kk * 128))[c4];
    }

    float acc[2][8][4];
#pragma unroll
    for (int rt = 0; rt < 2; rt++)
#pragma unroll
        for (int nt = 0; nt < 8; nt++)
#pragma unroll
            for (int j = 0; j < 4; j++) acc[rt][nt][j] = 0.f;

#pragma unroll
    for (int c = 0; c < 4; c++) {
        __syncthreads();
        if (!use_internal) {
            // fp32 x: 128 rows x 8 float4 = 1024 slots, 4 per thread
#pragma unroll
            for (int l = 0; l < 4; l++) {
                int idx = t + l * 256;
                int r = idx >> 3, c4 = idx & 7;
                int n = row0 + r;
                float4 v = (n < NN)
                    ? ((const float4*)(xext + n * 128 + c * 32))[c4]
                    : make_float4(0.f, 0.f, 0.f, 0.f);
                Xh[r][c4 * 2]     = pack_f16(v.x, v.y);
                Xh[r][c4 * 2 + 1] = pack_f16(v.z, v.w);
            }
        } else {
            // fp16 x (g_f2h): 128 rows x 4 uint4 = 512 slots, 2 per thread
#pragma unroll
            for (int l = 0; l < 2; l++) {
                int idx = t + l * 256;
                int r = idx >> 2, q4 = idx & 3;
                int n = row0 + r;
                uint4 u = (n < NN)
                    ? ((const uint4*)(g_f2h + n * 64 + c * 16))[q4]
                    : make_uint4(0u, 0u, 0u, 0u);
                *(uint4*)&Xh[r][q4 * 4] = u;
            }
        }
        __syncthreads();

        int kp0 = c * 16;
#pragma unroll
        for (int ks = 0; ks < 2; ks++) {
            int kb = ks * 8;
            unsigned a[2][4];
#pragma unroll
            for (int rt = 0; rt < 2; rt++) {
                int rb = wr + rt * 16;
                a[rt][0] = Xh[rb + gq][kb + qc];
                a[rt][1] = Xh[rb + gq + 8][kb + qc];
                a[rt][2] = Xh[rb + gq][kb + qc + 4];
                a[rt][3] = Xh[rb + gq + 8][kb + qc + 4];
            }
#pragma unroll
            for (int nt = 0; nt < 8; nt++) {
                int nb = wc + nt * 8 + gq;
                unsigned b0 = Whs[kp0 + kb + qc][nb];
                unsigned b1 = Whs[kp0 + kb + qc + 4][nb];
                MMA_F16(acc[0][nt], a[0][0], a[0][1], a[0][2], a[0][3], b0, b1);
                MMA_F16(acc[1][nt], a[1][0], a[1][1], a[1][2], a[1][3], b0, b1);
            }
        }
    }

    // ---- epilogue: store h (fp16), compute el/er for 2 heads, per row-tile --
    int hdb = wc >> 5;                    // head base: 0 (cols 0-63) or 2
#pragma unroll
    for (int rt = 0; rt < 2; rt++) {
        int n0 = row0 + wr + rt * 16 + gq;
        int n1 = n0 + 8;
        float pel0[2], per0[2], pel1[2], per1[2];
#pragma unroll
        for (int lh = 0; lh < 2; lh++) { pel0[lh] = per0[lh] = pel1[lh] = per1[lh] = 0.f; }

#pragma unroll
        for (int nt = 0; nt < 8; nt++) {
            int col = wc + nt * 8 + 2 * qc;
            float a0 = al[col], a1 = al[col + 1];
            float r0 = ar[col], r1 = ar[col + 1];
            int lh = nt >> 2;
            pel0[lh] += acc[rt][nt][0] * a0 + acc[rt][nt][1] * a1;
            per0[lh] += acc[rt][nt][0] * r0 + acc[rt][nt][1] * r1;
            pel1[lh] += acc[rt][nt][2] * a0 + acc[rt][nt][3] * a1;
            per1[lh] += acc[rt][nt][2] * r0 + acc[rt][nt][3] * r1;
            if (n0 < NN)
                g_hh[n0 * 64 + (col >> 1)] =
                    pack_f16(acc[rt][nt][0], acc[rt][nt][1]);
            if (n1 < NN)
                g_hh[n1 * 64 + (col >> 1)] =
                    pack_f16(acc[rt][nt][2], acc[rt][nt][3]);
        }
#pragma unroll
        for (int lh = 0; lh < 2; lh++) {
#pragma unroll
            for (int o = 1; o <= 2; o <<= 1) {
                pel0[lh] += __shfl_xor_sync(0xffffffffu, pel0[lh], o);
                per0[lh] += __shfl_xor_sync(0xffffffffu, per0[lh], o);
                pel1[lh] += __shfl_xor_sync(0xffffffffu, pel1[lh], o);
                per1[lh] += __shfl_xor_sync(0xffffffffu, per1[lh], o);
            }
        }
        if (qc == 0) {
#pragma unroll
            for (int lh = 0; lh < 2; lh++) {
                int hd = hdb + lh;
                if (n0 < NN) { g_el[n0 * 4 + hd] = pel0[lh]; g_er[n0 * 4 + hd] = per0[lh]; }
                if (n1 < NN) { g_el[n1 * 4 + hd] = pel1[lh]; g_er[n1 * 4 + hd] = per1[lh]; }
            }
        }
    }
}

// ---------------- fused softmax + aggregation: 2 nodes per warp -------------
// 16 lanes per node; lane covers 8 feats via one uint4 (fp16x8) per edge.
// No softmax shift needed: logits are O(5) (el,er each sigma~0.5), exp safe.
// Layer 1 writes fp16-packed g_f2h; layer 2 writes fp32 head-mean to out.
__global__ void __launch_bounds__(256) k_node(
    const float* __restrict__ b, float* __restrict__ out, int layer)
{
    int gwarp = (blockIdx.x * 256 + threadIdx.x) >> 5;
    int lane = threadIdx.x & 31;
    int half = lane >> 4, sl = lane & 15;
    int n = gwarp * 2 + half;
    bool act = n < NN;
    int hd = sl >> 2;

    int off = 0, deg = 0;
    if (act) {
        off = g_off[n];
        deg = g_off[n + 1] - off;
    }
    float erh = act ? g_er[n * 4 + hd] : 0.f;

    const int*   es = g_esrc + off;
    const uint4* hb = (const uint4*)g_hh;   // 16 uint4 per node
    const float* el = g_el;

    int dmax = max(deg, __shfl_xor_sync(0xffffffffu, deg, 16));

    float s = 0.f;
    float acc[8];
#pragma unroll
    for (int k = 0; k < 8; k++) acc[k] = 0.f;

    for (int j = 0; j < dmax; j += 4) {
        int s0 = (j + 0 < deg) ? es[j + 0] : -1;
        int s1 = (j + 1 < deg) ? es[j + 1] : -1;
        int s2 = (j + 2 < deg) ? es[j + 2] : -1;
        int s3 = (j + 3 < deg) ? es[j + 3] : -1;
        float e0 = (s0 >= 0) ? el[s0 * 4 + hd] : 0.f;
        float e1 = (s1 >= 0) ? el[s1 * 4 + hd] : 0.f;
        float e2 = (s2 >= 0) ? el[s2 * 4 + hd] : 0.f;
        float e3 = (s3 >= 0) ? el[s3 * 4 + hd] : 0.f;
        uint4 z = make_uint4(0u, 0u, 0u, 0u);
        uint4 p0 = (s0 >= 0) ? hb[s0 * 16 + sl] : z;
        uint4 p1 = (s1 >= 0) ? hb[s1 * 16 + sl] : z;
        uint4 p2 = (s2 >= 0) ? hb[s2 * 16 + sl] : z;
        uint4 p3 = (s3 >= 0) ? hb[s3 * 16 + sl] : z;
        float a0 = (s0 >= 0) ? __expf(lrelu(e0 + erh)) : 0.f;
        float a1 = (s1 >= 0) ? __expf(lrelu(e1 + erh)) : 0.f;
        float a2 = (s2 >= 0) ? __expf(lrelu(e2 + erh)) : 0.f;
        float a3 = (s3 >= 0) ? __expf(lrelu(e3 + erh)) : 0.f;
        s += (a0 + a1) + (a2 + a3);
        const unsigned* q0 = &p0.x;
        const unsigned* q1 = &p1.x;
        const unsigned* q2 = &p2.x;
        const unsigned* q3 = &p3.x;
#pragma unroll
        for (int k = 0; k < 4; k++) {
            float2 f0 = __half22float2(*reinterpret_cast<const __half2*>(&q0[k]));
            float2 f1 = __half22float2(*reinterpret_cast<const __half2*>(&q1[k]));
            float2 f2 = __half22float2(*reinterpret_cast<const __half2*>(&q2[k]));
            float2 f3 = __half22float2(*reinterpret_cast<const __half2*>(&q3[k]));
            acc[2 * k]     += (f0.x * a0 + f1.x * a1) + (f2.x * a2 + f3.x * a3);
            acc[2 * k + 1] += (f0.y * a0 + f1.y * a1) + (f2.y * a2 + f3.y * a3);
        }
    }

    float rinv = (act && deg > 0) ? 1.f / s : 0.f;
#pragma unroll
    for (int k = 0; k < 8; k++) acc[k] *= rinv;

    // bias: feats sl*8 .. sl*8+7
    float4 b0 = ((const float4*)b)[sl * 2];
    float4 b1 = ((const float4*)b)[sl * 2 + 1];
    acc[0] += b0.x; acc[1] += b0.y; acc[2] += b0.z; acc[3] += b0.w;
    acc[4] += b1.x; acc[5] += b1.y; acc[6] += b1.z; acc[7] += b1.w;

    if (layer == 1) {
        if (act) {
            uint4 o;
            o.x = pack_f16(fmaxf(acc[0], 0.f), fmaxf(acc[1], 0.f));
            o.y = pack_f16(fmaxf(acc[2], 0.f), fmaxf(acc[3], 0.f));
            o.z = pack_f16(fmaxf(acc[4], 0.f), fmaxf(acc[5], 0.f));
            o.w = pack_f16(fmaxf(acc[6], 0.f), fmaxf(acc[7], 0.f));
            ((uint4*)(g_f2h + n * 64 + sl * 4))[0] = o;
        }
    } else {
        // head mean: lanes {sl, sl^4, sl^8, sl^12} hold the 4 heads of the
        // same within-head offsets (sl&3)*8..+7
#pragma unroll
        for (int o = 4; o <= 8; o <<= 1) {
#pragma unroll
            for (int k = 0; k < 8; k++)
                acc[k] += __shfl_xor_sync(0xffffffffu, acc[k], o);
        }
        if (act && sl < 4) {
            float4 o0 = make_float4(acc[0] * 0.25f, acc[1] * 0.25f,
                                    acc[2] * 0.25f, acc[3] * 0.25f);
            float4 o1 = make_float4(acc[4] * 0.25f, acc[5] * 0.25f,
                                    acc[6] * 0.25f, acc[7] * 0.25f);
            float4* dst = (float4*)(out + n * 32 + sl * 8);
            dst[0] = o0; dst[1] = o1;
        }
    }
}

// ---------------- launch ---------------------------------------------------
extern "C" void kernel_launch(void* const* d_in, const int* in_sizes, int n_in,
                              void* d_out, int out_size)
{
    const float* feat = (const float*)d_in[0];
    const int*   src  = (const int*)d_in[1];
    const int*   dst  = (const int*)d_in[2];
    const float* W1   = (const float*)d_in[3];
    const float* al1  = (const float*)d_in[4];
    const float* ar1  = (const float*)d_in[5];
    const float* b1   = (const float*)d_in[6];
    const float* W2   = (const float*)d_in[7];
    const float* al2  = (const float*)d_in[8];
    const float* ar2  = (const float*)d_in[9];
    const float* b2   = (const float*)d_in[10];
    float* out = (float*)d_out;

    const int G_E    = (EE + 255) / 256;
    const int G_GEMM = (NN + 127) / 128;
    const int G_NODE = ((NN + 1) / 2 * 32 + 255) / 256;   // 2 nodes per warp

    k_pc<<<G_E, 256>>>(W1, W2, dst);                     // 0
    k_scan<<<NB, 1024>>>();                              // 1
    k_fill<<<G_E, 256>>>(src, dst);                      // 2
    k_gemm_tc<<<G_GEMM, 256>>>(feat, 0, 0, al1, ar1);    // 3
    k_node<<<G_NODE, 256>>>(b1, nullptr, 1);             // 4
    k_gemm_tc<<<G_GEMM, 256>>>(nullptr, 1, 1, al2, ar2); // 5
    k_node<<<G_NODE, 256>>>(b2, out, 2);                 // 6
}

// round 17
// speedup vs baseline: 1.0922x; 1.0645x over previous
#include <cuda_runtime.h>
#include <cuda_fp16.h>

#define NN 100000
#define EE 800000
#define NB 98            // scan blocks: ceil(100000/1024)

// ---------------- scratch (device globals; BSS = zero-initialized) ----------
__device__ unsigned g_hh[NN * 64];      // projected features, packed half2 (fp16)
__device__ unsigned g_f2h[NN * 64];     // layer-2 input, packed half2 (fp16, kpairs)
__device__ float    g_el[NN * 4];
__device__ float    g_er[NN * 4];
__device__ int      g_cnt[NN];          // INVARIANT: zero at entry of each call
__device__ int      g_off[NN + 1];      // CSR row offsets (by dst)
__device__ int      g_rank[EE];         // intra-node rank of each edge
__device__ int      g_esrc[EE];         // src node per CSR slot
__device__ int      g_bsum[NB];
__device__ int      g_ctr;              // grid-barrier counter; self-resets to 0
// W as packed fp16 pairs (k, k+1) along K: [layer][ (k/2)*128 + n ]
__device__ unsigned g_Wh[2][64 * 128];

__device__ __forceinline__ float lrelu(float v) { return v > 0.f ? v : 0.2f * v; }

// pack two fp32 into one f16x2 (low half = x0, high half = x1)
__device__ __forceinline__ unsigned pack_f16(float x0, float x1) {
    unsigned p;
    asm("cvt.rn.f16x2.f32 %0, %1, %2;" : "=r"(p) : "f"(x1), "f"(x0));
    return p;
}

#define MMA_F16(c, a0, a1, a2, a3, b0, b1)                                     \
    asm volatile(                                                              \
        "mma.sync.aligned.m16n8k16.row.col.f32.f16.f16.f32 "                   \
        "{%0,%1,%2,%3}, {%4,%5,%6,%7}, {%8,%9}, {%0,%1,%2,%3};"                \
        : "+f"(c[0]), "+f"(c[1]), "+f"(c[2]), "+f"(c[3])                       \
        : "r"(a0), "r"(a1), "r"(a2), "r"(a3), "r"(b0), "r"(b1))

// ---------------- fused: W pack (fp16) + edge count/rank --------------------
__global__ void k_pc(const float* __restrict__ W1, const float* __restrict__ W2,
                     const int* __restrict__ dst) {
    int i = blockIdx.x * 256 + threadIdx.x;
    if (i < 2 * 64 * 128) {
        int which = i >> 13, j = i & 8191;
        int kp = j >> 7, n = j & 127;
        const float* W = which == 0 ? W1 : W2;
        g_Wh[which][kp * 128 + n] =
            pack_f16(W[(2 * kp) * 128 + n], W[(2 * kp + 1) * 128 + n]);
    }
    if (i < EE) g_rank[i] = atomicAdd(&g_cnt[dst[i]], 1);
}

// ---------------- single-kernel CSR offset scan (grid barrier) --------------
__global__ void __launch_bounds__(1024) k_scan() {
    __shared__ int sh[1024];
    __shared__ int bs[128];
    int t = threadIdx.x, i = blockIdx.x * 1024 + t;
    int v = (i < NN) ? g_cnt[i] : 0;
    if (i < NN) g_cnt[i] = 0;               // restore invariant for next call
    sh[t] = v; __syncthreads();
#pragma unroll
    for (int d = 1; d < 1024; d <<= 1) {
        int add = (t >= d) ? sh[t - d] : 0;
        __syncthreads();
        sh[t] += add;
        __syncthreads();
    }
    if (t == 1023) {
        g_bsum[blockIdx.x] = sh[1023];
        __threadfence();
        atomicAdd(&g_ctr, 1);
    }
    if (t == 0) {
        while (*(volatile int*)&g_ctr < NB) { }
        __threadfence();
    }
    __syncthreads();
    if (t < 128) bs[t] = (t < NB) ? g_bsum[t] : 0;
    __syncthreads();
#pragma unroll
    for (int d = 1; d < 128; d <<= 1) {
        int add = 0;
        if (t < 128 && t >= d) add = bs[t - d];
        __syncthreads();
        if (t < 128) bs[t] += add;
        __syncthreads();
    }
    int add = blockIdx.x > 0 ? bs[blockIdx.x - 1] : 0;
    if (i < NN) g_off[i] = sh[t] - v + add;   // exclusive prefix
    if (i == 0) g_off[NN] = EE;
    __syncthreads();
    if (t == 0) {
        int old = atomicAdd(&g_ctr, 1);       // phase-2 count: NB..2*NB
        if (old == 2 * NB - 1) atomicExch(&g_ctr, 0);   // last block resets
    }
}

// fill without atomics: position = off[dst] + rank
__global__ void k_fill(const int* __restrict__ src, const int* __restrict__ dst) {
    int e = blockIdx.x * 256 + threadIdx.x;
    if (e >= EE) return;
    int p = g_off[dst[e]] + g_rank[e];
    g_esrc[p] = src[e];
}

// ---------------- tensor-core projection GEMM (fp16, single-phase) ----------
// 128 rows x 128 cols per block; 8 warps 4(row)x2(col); warp = 32 rows x 64
// cols. ALL of X and W staged in smem in one load burst (max MLP), one sync,
// then an uninterrupted MMA stream. Co-resident block overlaps its load burst
// with this block's compute. Layer 1 reads fp32 x; layer 2 reads fp16 g_f2h.
__global__ void __launch_bounds__(256, 2) k_gemm_tc(
    const float* __restrict__ xext, int use_internal, int widx,
    const float* __restrict__ al, const float* __restrict__ ar)
{
    const unsigned* Wg = g_Wh[widx];

    __shared__ unsigned Whs[64][136];     // full W: 64 kpairs x 128 n (+8 pad)
    __shared__ unsigned Xh[128][68];      // full X: 128 rows x 64 kpairs (+4 pad)

    int t = threadIdx.x;
    int lane = t & 31, w = t >> 5;
    int row0 = blockIdx.x * 128;
    int wr = (w >> 1) * 32;            // warp row base (4 row groups of 32)
    int wc = (w & 1) * 64;             // warp col base (2 col halves)
    int gq = lane >> 2, qc = lane & 3;

    // full W load: 2048 uint4 over 256 threads = 8 each
#pragma unroll
    for (int l = 0; l < 8; l++) {
        int idx = t + l * 256;
        int kk = idx >> 5, c4 = idx & 31;
        *(uint4*)&Whs[kk][c4 * 4] = ((const uint4*)(Wg + kk * 128))[c4];
    }
    // full X load in one burst
    if (!use_internal) {
        // fp32 x: 128 rows x 32 float4 = 4096, 16 per thread
#pragma unroll
        for (int l = 0; l < 16; l++) {
            int idx = t + l * 256;
            int r = idx >> 5, c4 = idx & 31;
            int n = row0 + r;
            float4 v = (n < NN) ? ((const float4*)(xext + n * 128))[c4]
                                : make_float4(0.f, 0.f, 0.f, 0.f);
            Xh[r][c4 * 2]     = pack_f16(v.x, v.y);
            Xh[r][c4 * 2 + 1] = pack_f16(v.z, v.w);
        }
    } else {
        // fp16 x (g_f2h): 128 rows x 16 uint4 = 2048, 8 per thread
#pragma unroll
        for (int l = 0; l < 8; l++) {
            int idx = t + l * 256;
            int r = idx >> 4, q4 = idx & 15;
            int n = row0 + r;
            uint4 u = (n < NN) ? ((const uint4*)(g_f2h + n * 64))[q4]
                               : make_uint4(0u, 0u, 0u, 0u);
            *(uint4*)&Xh[r][q4 * 4] = u;
        }
    }

    float acc[2][8][4];
#pragma unroll
    for (int rt = 0; rt < 2; rt++)
#pragma unroll
        for (int nt = 0; nt < 8; nt++)
#pragma unroll
            for (int j = 0; j < 4; j++) acc[rt][nt][j] = 0.f;

    __syncthreads();

#pragma unroll
    for (int ks = 0; ks < 8; ks++) {
        int kb = ks * 8;
        unsigned a[2][4];
#pragma unroll
        for (int rt = 0; rt < 2; rt++) {
            int rb = wr + rt * 16;
            a[rt][0] = Xh[rb + gq][kb + qc];
            a[rt][1] = Xh[rb + gq + 8][kb + qc];
            a[rt][2] = Xh[rb + gq][kb + qc + 4];
            a[rt][3] = Xh[rb + gq + 8][kb + qc + 4];
        }
#pragma unroll
        for (int nt = 0; nt < 8; nt++) {
            int nb = wc + nt * 8 + gq;
            unsigned b0 = Whs[kb + qc][nb];
            unsigned b1 = Whs[kb + qc + 4][nb];
            MMA_F16(acc[0][nt], a[0][0], a[0][1], a[0][2], a[0][3], b0, b1);
            MMA_F16(acc[1][nt], a[1][0], a[1][1], a[1][2], a[1][3], b0, b1);
        }
    }

    // ---- epilogue: store h (fp16), compute el/er for 2 heads, per row-tile --
    int hdb = wc >> 5;                    // head base: 0 (cols 0-63) or 2
#pragma unroll
    for (int rt = 0; rt < 2; rt++) {
        int n0 = row0 + wr + rt * 16 + gq;
        int n1 = n0 + 8;
        float pel0[2], per0[2], pel1[2], per1[2];
#pragma unroll
        for (int lh = 0; lh < 2; lh++) { pel0[lh] = per0[lh] = pel1[lh] = per1[lh] = 0.f; }

#pragma unroll
        for (int nt = 0; nt < 8; nt++) {
            int col = wc + nt * 8 + 2 * qc;
            float a0 = al[col], a1 = al[col + 1];
            float r0 = ar[col], r1 = ar[col + 1];
            int lh = nt >> 2;
            pel0[lh] += acc[rt][nt][0] * a0 + acc[rt][nt][1] * a1;
            per0[lh] += acc[rt][nt][0] * r0 + acc[rt][nt][1] * r1;
            pel1[lh] += acc[rt][nt][2] * a0 + acc[rt][nt][3] * a1;
            per1[lh] += acc[rt][nt][2] * r0 + acc[rt][nt][3] * r1;
            if (n0 < NN)
                g_hh[n0 * 64 + (col >> 1)] =
                    pack_f16(acc[rt][nt][0], acc[rt][nt][1]);
            if (n1 < NN)
                g_hh[n1 * 64 + (col >> 1)] =
                    pack_f16(acc[rt][nt][2], acc[rt][nt][3]);
        }
#pragma unroll
        for (int lh = 0; lh < 2; lh++) {
#pragma unroll
            for (int o = 1; o <= 2; o <<= 1) {
                pel0[lh] += __shfl_xor_sync(0xffffffffu, pel0[lh], o);
                per0[lh] += __shfl_xor_sync(0xffffffffu, per0[lh], o);
                pel1[lh] += __shfl_xor_sync(0xffffffffu, pel1[lh], o);
                per1[lh] += __shfl_xor_sync(0xffffffffu, per1[lh], o);
            }
        }
        if (qc == 0) {
#pragma unroll
            for (int lh = 0; lh < 2; lh++) {
                int hd = hdb + lh;
                if (n0 < NN) { g_el[n0 * 4 + hd] = pel0[lh]; g_er[n0 * 4 + hd] = per0[lh]; }
                if (n1 < NN) { g_el[n1 * 4 + hd] = pel1[lh]; g_er[n1 * 4 + hd] = per1[lh]; }
            }
        }
    }
}

// ---------------- fused softmax + aggregation: 2 nodes per warp -------------
// 16 lanes per node; lane covers 8 feats via one uint4 (fp16x8) per edge.
// No softmax shift needed: logits are O(5) (el,er each sigma~0.5), exp safe.
// Layer 1 writes fp16-packed g_f2h; layer 2 writes fp32 head-mean to out.
__global__ void __launch_bounds__(256) k_node(
    const float* __restrict__ b, float* __restrict__ out, int layer)
{
    int gwarp = (blockIdx.x * 256 + threadIdx.x) >> 5;
    int lane = threadIdx.x & 31;
    int half = lane >> 4, sl = lane & 15;
    int n = gwarp * 2 + half;
    bool act = n < NN;
    int hd = sl >> 2;

    int off = 0, deg = 0;
    if (act) {
        off = g_off[n];
        deg = g_off[n + 1] - off;
    }
    float erh = act ? g_er[n * 4 + hd] : 0.f;

    const int*   es = g_esrc + off;
    const uint4* hb = (const uint4*)g_hh;   // 16 uint4 per node
    const float* el = g_el;

    int dmax = max(deg, __shfl_xor_sync(0xffffffffu, deg, 16));

    float s = 0.f;
    float acc[8];
#pragma unroll
    for (int k = 0; k < 8; k++) acc[k] = 0.f;

    for (int j = 0; j < dmax; j += 4) {
        int s0 = (j + 0 < deg) ? es[j + 0] : -1;
        int s1 = (j + 1 < deg) ? es[j + 1] : -1;
        int s2 = (j + 2 < deg) ? es[j + 2] : -1;
        int s3 = (j + 3 < deg) ? es[j + 3] : -1;
        float e0 = (s0 >= 0) ? el[s0 * 4 + hd] : 0.f;
        float e1 = (s1 >= 0) ? el[s1 * 4 + hd] : 0.f;
        float e2 = (s2 >= 0) ? el[s2 * 4 + hd] : 0.f;
        float e3 = (s3 >= 0) ? el[s3 * 4 + hd] : 0.f;
        uint4 z = make_uint4(0u, 0u, 0u, 0u);
        uint4 p0 = (s0 >= 0) ? hb[s0 * 16 + sl] : z;
        uint4 p1 = (s1 >= 0) ? hb[s1 * 16 + sl] : z;
        uint4 p2 = (s2 >= 0) ? hb[s2 * 16 + sl] : z;
        uint4 p3 = (s3 >= 0) ? hb[s3 * 16 + sl] : z;
        float a0 = (s0 >= 0) ? __expf(lrelu(e0 + erh)) : 0.f;
        float a1 = (s1 >= 0) ? __expf(lrelu(e1 + erh)) : 0.f;
        float a2 = (s2 >= 0) ? __expf(lrelu(e2 + erh)) : 0.f;
        float a3 = (s3 >= 0) ? __expf(lrelu(e3 + erh)) : 0.f;
        s += (a0 + a1) + (a2 + a3);
        const unsigned* q0 = &p0.x;
        const unsigned* q1 = &p1.x;
        const unsigned* q2 = &p2.x;
        const unsigned* q3 = &p3.x;
#pragma unroll
        for (int k = 0; k < 4; k++) {
            float2 f0 = __half22float2(*reinterpret_cast<const __half2*>(&q0[k]));
            float2 f1 = __half22float2(*reinterpret_cast<const __half2*>(&q1[k]));
            float2 f2 = __half22float2(*reinterpret_cast<const __half2*>(&q2[k]));
            float2 f3 = __half22float2(*reinterpret_cast<const __half2*>(&q3[k]));
            acc[2 * k]     += (f0.x * a0 + f1.x * a1) + (f2.x * a2 + f3.x * a3);
            acc[2 * k + 1] += (f0.y * a0 + f1.y * a1) + (f2.y * a2 + f3.y * a3);
        }
    }

    float rinv = (act && deg > 0) ? 1.f / s : 0.f;
#pragma unroll
    for (int k = 0; k < 8; k++) acc[k] *= rinv;

    // bias: feats sl*8 .. sl*8+7
    float4 b0 = ((const float4*)b)[sl * 2];
    float4 b1 = ((const float4*)b)[sl * 2 + 1];
    acc[0] += b0.x; acc[1] += b0.y; acc[2] += b0.z; acc[3] += b0.w;
    acc[4] += b1.x; acc[5] += b1.y; acc[6] += b1.z; acc[7] += b1.w;

    if (layer == 1) {
        if (act) {
            uint4 o;
            o.x = pack_f16(fmaxf(acc[0], 0.f), fmaxf(acc[1], 0.f));
            o.y = pack_f16(fmaxf(acc[2], 0.f), fmaxf(acc[3], 0.f));
            o.z = pack_f16(fmaxf(acc[4], 0.f), fmaxf(acc[5], 0.f));
            o.w = pack_f16(fmaxf(acc[6], 0.f), fmaxf(acc[7], 0.f));
            ((uint4*)(g_f2h + n * 64 + sl * 4))[0] = o;
        }
    } else {
        // head mean: lanes {sl, sl^4, sl^8, sl^12} hold the 4 heads of the
        // same within-head offsets (sl&3)*8..+7
#pragma unroll
        for (int o = 4; o <= 8; o <<= 1) {
#pragma unroll
            for (int k = 0; k < 8; k++)
                acc[k] += __shfl_xor_sync(0xffffffffu, acc[k], o);
        }
        if (act && sl < 4) {
            float4 o0 = make_float4(acc[0] * 0.25f, acc[1] * 0.25f,
                                    acc[2] * 0.25f, acc[3] * 0.25f);
            float4 o1 = make_float4(acc[4] * 0.25f, acc[5] * 0.25f,
                                    acc[6] * 0.25f, acc[7] * 0.25f);
            float4* dst = (float4*)(out + n * 32 + sl * 8);
            dst[0] = o0; dst[1] = o1;
        }
    }
}

// ---------------- launch ---------------------------------------------------
extern "C" void kernel_launch(void* const* d_in, const int* in_sizes, int n_in,
                              void* d_out, int out_size)
{
    const float* feat = (const float*)d_in[0];
    const int*   src  = (const int*)d_in[1];
    const int*   dst  = (const int*)d_in[2];
    const float* W1   = (const float*)d_in[3];
    const float* al1  = (const float*)d_in[4];
    const float* ar1  = (const float*)d_in[5];
    const float* b1   = (const float*)d_in[6];
    const float* W2   = (const float*)d_in[7];
    const float* al2  = (const float*)d_in[8];
    const float* ar2  = (const float*)d_in[9];
    const float* b2   = (const float*)d_in[10];
    float* out = (float*)d_out;

    const int G_E    = (EE + 255) / 256;
    const int G_GEMM = (NN + 127) / 128;
    const int G_NODE = ((NN + 1) / 2 * 32 + 255) / 256;   // 2 nodes per warp

    k_pc<<<G_E, 256>>>(W1, W2, dst);                     // 0
    k_scan<<<NB, 1024>>>();                              // 1
    k_fill<<<G_E, 256>>>(src, dst);                      // 2
    k_gemm_tc<<<G_GEMM, 256>>>(feat, 0, 0, al1, ar1);    // 3
    k_node<<<G_NODE, 256>>>(b1, nullptr, 1);             // 4
    k_gemm_tc<<<G_GEMM, 256>>>(nullptr, 1, 1, al2, ar2); // 5
    k_node<<<G_NODE, 256>>>(b2, out, 2);                 // 6
}